// round 16
// baseline (speedup 1.0000x reference)
#include <cuda_runtime.h>
#include <cuda_fp16.h>

// ---------------------------------------------------------------------------
// KPlaneRBFField on GB300 — round 16.
//  Field/prep identical to R15. Sort refined 32^3 -> 64^3 Morton buckets
//  (18-bit keys): warp's 8 points now span ~4 buckets (~2 texels at scale-0)
//  -> plane corner loads share 128B lines within each LDG -> fewer L1tex
//  wavefronts in the field kernel (the measured binder at 82%).
// ---------------------------------------------------------------------------

#define NSIDE 64
#define MAXN  524288
#define NBUCK 262144          // 64^3 Morton buckets
#define TP_POS 256

__device__ __half   g_planesTh[33030144];  // 66 MB transposed fp16 planes
__device__ __half   g_lc0h[8388608];       // 16.5 MB fp16 codes
__device__ unsigned g_hist[NBUCK];         // 1 MB
__device__ unsigned g_blksum[32];
__device__ unsigned g_key[MAXN];
__device__ float4   g_spts[MAXN];          // sorted (xs0,xs1,xs2,pid)

__constant__ int c_plane_off[9] = {
    0,        524288,   1048576,
    1572864,  3670016,  5767168,
    7864320,  16252928, 24641536
};
// blocks/plane @256 pos: {64,64,64,256,256,256,1024,1024,1024}
__constant__ int c_blkCum[10] = {0,64,128,192,448,704,960,1984,3008,4032};
__constant__ int c_res[9]     = {128,128,128,256,256,256,512,512,512};

#define LC0_BLK_END 12224   // 4032 + 8192

struct PrepArgs {
    const float* p[9];
    const float* lc0;
    const float* pts;
    const float* aabb;
    int n;
};

__device__ __forceinline__ unsigned spread3(unsigned x)
{
    x &= 0x3FF;
    x = (x | (x << 16)) & 0x30000FF;
    x = (x | (x << 8))  & 0x300F00F;
    x = (x | (x << 4))  & 0x30C30C3;
    x = (x | (x << 2))  & 0x9249249;
    return x;
}

// ---------------- k1: transpose + lc0 convert + histogram -------------------
__global__ void __launch_bounds__(256) prep_kernel(PrepArgs a)
{
    int b = blockIdx.x;
    int tid = threadIdx.x;

    if (b >= LC0_BLK_END) {                 // Morton histogram (64/dim)
        int i = (b - LC0_BLK_END) * 256 + tid;
        if (i >= a.n) return;
        float a0x = a.aabb[0], a0y = a.aabb[1], a0z = a.aabb[2];
        float a1x = a.aabb[3], a1y = a.aabb[4], a1z = a.aabb[5];
        float x = (a.pts[3 * i + 0] - a0x) * (2.0f / (a1x - a0x)) - 1.0f;
        float y = (a.pts[3 * i + 1] - a0y) * (2.0f / (a1y - a0y)) - 1.0f;
        float z = (a.pts[3 * i + 2] - a0z) * (2.0f / (a1z - a0z)) - 1.0f;
        int qx = min(max((int)((x + 1.0f) * 32.0f), 0), 63);
        int qy = min(max((int)((y + 1.0f) * 32.0f), 0), 63);
        int qz = min(max((int)((z + 1.0f) * 32.0f), 0), 63);
        unsigned key = (spread3(qx) << 2) | (spread3(qy) << 1) | spread3(qz);
        g_key[i] = key;
        atomicAdd(&g_hist[key], 1u);
        return;
    }
    if (b >= 4032) {                        // lc0 convert (8192 blocks)
        int i = (b - 4032) * 256 + tid;
        float4 v = __ldcs((const float4*)a.lc0 + i);
        __half2 h0 = __floats2half2_rn(v.x, v.y);
        __half2 h1 = __floats2half2_rn(v.z, v.w);
        ((uint2*)g_lc0h)[i] = make_uint2(*(unsigned*)&h0, *(unsigned*)&h1);
        return;
    }

    // plane transpose: 256 positions per block, conflict-free smem.
    __shared__ float tile[TP_POS][33];
    int pi = 0;
    #pragma unroll
    for (int i = 1; i < 9; i++) pi += (b >= c_blkCum[i]) ? 1 : 0;
    int rr = c_res[pi] * c_res[pi];
    int posBase = (b - c_blkCum[pi]) * TP_POS;
    const float* src = a.p[pi];

    float va[32];
    #pragma unroll
    for (int it = 0; it < 32; it++)
        va[it] = __ldcs(&src[it * rr + posBase + tid]);
    #pragma unroll
    for (int it = 0; it < 32; it++)
        tile[tid][it] = va[it];
    __syncthreads();

    uint2* dst2 = (uint2*)(g_planesTh + c_plane_off[pi]) + posBase * 8;
    #pragma unroll
    for (int it = 0; it < 8; it++) {
        int v  = tid + it * 256;            // = p*8 + c4idx
        int p  = v >> 3;
        int c4 = (v & 7) << 2;
        __half2 h0 = __floats2half2_rn(tile[p][c4 + 0], tile[p][c4 + 1]);
        __half2 h1 = __floats2half2_rn(tile[p][c4 + 2], tile[p][c4 + 3]);
        dst2[v] = make_uint2(*(unsigned*)&h0, *(unsigned*)&h1);
    }
}

// ---------------- k2: scan of 262144 buckets (32 blocks x 1024 x 8) ----------
__global__ void __launch_bounds__(1024) scan1_kernel()
{
    __shared__ unsigned wsum[32];
    int t = threadIdx.x;
    int lane = t & 31;
    int wid = t >> 5;
    int base = blockIdx.x * 8192 + t * 8;

    unsigned v[8];
    unsigned sum = 0;
    #pragma unroll
    for (int j = 0; j < 8; j++) {
        v[j] = g_hist[base + j];
        sum += v[j];
    }

    unsigned x = sum;
    #pragma unroll
    for (int off = 1; off < 32; off <<= 1) {
        unsigned y = __shfl_up_sync(0xFFFFFFFFu, x, off);
        if (lane >= off) x += y;
    }
    if (lane == 31) wsum[wid] = x;
    __syncthreads();
    if (wid == 0) {
        unsigned w = wsum[lane];
        unsigned ww = w;
        #pragma unroll
        for (int off = 1; off < 32; off <<= 1) {
            unsigned y = __shfl_up_sync(0xFFFFFFFFu, ww, off);
            if (lane >= off) ww += y;
        }
        wsum[lane] = ww - w;
        if (lane == 31) g_blksum[blockIdx.x] = ww;
    }
    __syncthreads();

    unsigned run = x - sum + wsum[wid];     // exclusive prefix for this thread
    #pragma unroll
    for (int j = 0; j < 8; j++) {
        unsigned vv = v[j];
        g_hist[base + j] = run;
        run += vv;
    }
}

// ---------------- k3: scatter -------------------------------------------------
__global__ void scatter_kernel(const float* __restrict__ pts,
                               const float* __restrict__ aabb, int n)
{
    __shared__ unsigned blkoff[32];
    int t = threadIdx.x;
    if (t < 32) {
        unsigned v = g_blksum[t];
        unsigned x = v;
        #pragma unroll
        for (int off = 1; off < 32; off <<= 1) {
            unsigned y = __shfl_up_sync(0xFFFFFFFFu, x, off);
            if (t >= off) x += y;
        }
        blkoff[t] = x - v;
    }
    __syncthreads();

    int i = blockIdx.x * blockDim.x + t;
    if (i >= n) return;
    unsigned key = g_key[i];
    unsigned pos = atomicAdd(&g_hist[key], 1u) + blkoff[key >> 13];

    float a0x = aabb[0], a0y = aabb[1], a0z = aabb[2];
    float a1x = aabb[3], a1y = aabb[4], a1z = aabb[5];
    float xs0 = (pts[3 * i + 0] - a0x) * (2.0f / (a1x - a0x)) - 1.0f;
    float xs1 = (pts[3 * i + 1] - a0y) * (2.0f / (a1y - a0y)) - 1.0f;
    float xs2 = (pts[3 * i + 2] - a0z) * (2.0f / (a1z - a0z)) - 1.0f;
    g_spts[pos] = make_float4(xs0, xs1, xs2, __int_as_float(i));
}

__global__ void ident_kernel(const float* __restrict__ pts,
                             const float* __restrict__ aabb, int n)
{
    int i = blockIdx.x * blockDim.x + threadIdx.x;
    if (i >= n) return;
    float a0x = aabb[0], a0y = aabb[1], a0z = aabb[2];
    float a1x = aabb[3], a1y = aabb[4], a1z = aabb[5];
    float xs0 = (pts[3 * i + 0] - a0x) * (2.0f / (a1x - a0x)) - 1.0f;
    float xs1 = (pts[3 * i + 1] - a0y) * (2.0f / (a1y - a0y)) - 1.0f;
    float xs2 = (pts[3 * i + 2] - a0z) * (2.0f / (a1z - a0z)) - 1.0f;
    g_spts[i] = make_float4(xs0, xs1, xs2, __int_as_float(i));
}

// ---------------- fp16 helpers ----------------------------------------------
__device__ __forceinline__ void h8tof8(uint4 u, float* f)
{
    float2 p;
    p = __half22float2(*(const __half2*)&u.x); f[0] = p.x; f[1] = p.y;
    p = __half22float2(*(const __half2*)&u.y); f[2] = p.x; f[3] = p.y;
    p = __half22float2(*(const __half2*)&u.z); f[4] = p.x; f[5] = p.y;
    p = __half22float2(*(const __half2*)&u.w); f[6] = p.x; f[7] = p.y;
}

// one bilinear sample of 8 channels: 4 LDG.128, x-lerp half2, y-lerp fp32.
__device__ __forceinline__ void sample8(const __half* __restrict__ T, int r,
                                        float u, float v, int c8, float* f)
{
    float fr = (float)(r - 1);
    float fx = (u + 1.0f) * 0.5f * fr;
    float fy = (v + 1.0f) * 0.5f * fr;
    float flx = fminf(fmaxf(floorf(fx), 0.0f), (float)(r - 2));
    float fly = fminf(fmaxf(floorf(fy), 0.0f), (float)(r - 2));
    float wx = fx - flx;
    float wy = fy - fly;
    int ix = (int)flx;
    int iy = (int)fly;
    const uint4* b = (const uint4*)(T + ((iy * r + ix) << 5)) + c8;
    int rs = r << 2;
    uint4 A = __ldg(b);
    uint4 B = __ldg(b + 4);
    uint4 C = __ldg(b + rs);
    uint4 D = __ldg(b + rs + 4);

    __half2 wx2 = __float2half2_rn(wx);
    const __half2* Ah = (const __half2*)&A;
    const __half2* Bh = (const __half2*)&B;
    const __half2* Ch = (const __half2*)&C;
    const __half2* Dh = (const __half2*)&D;
    #pragma unroll
    for (int i = 0; i < 4; i++) {
        __half2 t = __hfma2(__hsub2(Bh[i], Ah[i]), wx2, Ah[i]);
        __half2 o = __hfma2(__hsub2(Dh[i], Ch[i]), wx2, Ch[i]);
        float2 tf = __half22float2(t);
        float2 bf = __half22float2(o);
        f[2 * i + 0] = tf.x + (bf.x - tf.x) * wy;
        f[2 * i + 1] = tf.y + (bf.y - tf.y) * wy;
    }
}

// ---------------- k4: field kernel (R10): 8 pts/warp, 50% occ ----------------
__global__ void __launch_bounds__(256, 4) field_kernel(
    const float* __restrict__ ks,
    const float* __restrict__ kpb,
    float* __restrict__ out,
    int npts)
{
    int gwarp = (int)((blockIdx.x * blockDim.x + threadIdx.x) >> 5);
    int lane  = threadIdx.x & 31;
    int pslot = lane >> 2;
    int c8    = lane & 3;

    int slot = gwarp * 8 + pslot;
    if (slot >= npts) return;

    float4 sp = __ldcs(&g_spts[slot]);
    float xs0 = sp.x, xs1 = sp.y, xs2 = sp.z;
    int pid = __float_as_int(sp.w);

    float* outP = out + (size_t)pid * 128;
    const float4* kpb4 = (const float4*)kpb;

    const int resArr[3] = {128, 256, 512};
    #pragma unroll
    for (int s = 0; s < 3; s++) {
        int r = resArr[s];
        float f0[8], f1[8], f2[8];
        sample8(g_planesTh + c_plane_off[s * 3 + 0], r, xs0, xs1, c8, f0);
        sample8(g_planesTh + c_plane_off[s * 3 + 1], r, xs0, xs2, c8, f1);
        sample8(g_planesTh + c_plane_off[s * 3 + 2], r, xs1, xs2, c8, f2);
        float4 bb0 = __ldg(kpb4 + s * 8 + c8 * 2);
        float4 bb1 = __ldg(kpb4 + s * 8 + c8 * 2 + 1);
        float4 o0, o1;
        o0.x = f0[0] * f1[0] * f2[0] + bb0.x;
        o0.y = f0[1] * f1[1] * f2[1] + bb0.y;
        o0.z = f0[2] * f1[2] * f2[2] + bb0.z;
        o0.w = f0[3] * f1[3] * f2[3] + bb0.w;
        o1.x = f0[4] * f1[4] * f2[4] + bb1.x;
        o1.y = f0[5] * f1[5] * f2[5] + bb1.y;
        o1.z = f0[6] * f1[6] * f2[6] + bb1.z;
        o1.w = f0[7] * f1[7] * f2[7] + bb1.w;
        float* op = outP + s * 32 + (c8 << 3);
        __stcs((float4*)op, o0);
        __stcs((float4*)(op + 4), o1);
    }

    // ---- RBF features over 64^3 grid on [-1,1]
    const float interval = 2.0f / (float)(NSIDE - 1);
    float c0f = fminf(fmaxf(floorf((xs0 + 1.0f) / interval), 0.0f), (float)(NSIDE - 2));
    float c1f = fminf(fmaxf(floorf((xs1 + 1.0f) / interval), 0.0f), (float)(NSIDE - 2));
    float c2f = fminf(fmaxf(floorf((xs2 + 1.0f) / interval), 0.0f), (float)(NSIDE - 2));
    int ci0 = (int)c0f, ci1 = (int)c1f, ci2 = (int)c2f;

    float acc[8] = {0.f, 0.f, 0.f, 0.f, 0.f, 0.f, 0.f, 0.f};
    float wsum = 0.0f;
    #pragma unroll
    for (int g = 0; g < 2; g++) {
        int idxA[4];
        float d2A[4];
        #pragma unroll
        for (int q = 0; q < 4; q++) {
            int k = g * 4 + q;
            int i0 = ci0 + ((k >> 2) & 1);
            int i1 = ci1 + ((k >> 1) & 1);
            int i2 = ci2 + (k & 1);
            idxA[q] = (i0 * NSIDE + i1) * NSIDE + i2;
            float d0 = xs0 - (-1.0f + (float)i0 * interval);
            float d1 = xs1 - (-1.0f + (float)i1 * interval);
            float d2 = xs2 - (-1.0f + (float)i2 * interval);
            d2A[q] = d0 * d0 + d1 * d1 + d2 * d2;
        }
        float svA[4];
        uint4 cuA[4];
        #pragma unroll
        for (int q = 0; q < 4; q++) {
            svA[q] = __ldg(&ks[idxA[q]]);
            cuA[q] = __ldg((const uint4*)(g_lc0h + (idxA[q] << 5)) + c8);
        }
        #pragma unroll
        for (int q = 0; q < 4; q++) {
            float phi = 1.0f / (1.0f + d2A[q] * svA[q] * svA[q]);
            wsum += phi;
            float code[8];
            h8tof8(cuA[q], code);
            #pragma unroll
            for (int j = 0; j < 8; j++) acc[j] += phi * code[j];
        }
    }
    float inv = 1.0f / (wsum + 1e-8f);
    float4 bb0 = __ldg(kpb4 + 24 + c8 * 2);
    float4 bb1 = __ldg(kpb4 + 24 + c8 * 2 + 1);
    float4 o0, o1;
    o0.x = acc[0] * inv + bb0.x;
    o0.y = acc[1] * inv + bb0.y;
    o0.z = acc[2] * inv + bb0.z;
    o0.w = acc[3] * inv + bb0.w;
    o1.x = acc[4] * inv + bb1.x;
    o1.y = acc[5] * inv + bb1.y;
    o1.z = acc[6] * inv + bb1.z;
    o1.w = acc[7] * inv + bb1.w;
    float* op = outP + 96 + (c8 << 3);
    __stcs((float4*)op, o0);
    __stcs((float4*)(op + 4), o1);
}

// ------------------------------ launcher ------------------------------------
extern "C" void kernel_launch(void* const* d_in, const int* in_sizes, int n_in,
                              void* d_out, int out_size)
{
    const float* pts  = (const float*)d_in[0];
    const float* aabb = (const float*)d_in[1];
    const float* lc0  = (const float*)d_in[11];
    const float* ks   = (const float*)d_in[12];
    const float* kpb  = (const float*)d_in[13];
    float* out = (float*)d_out;

    int npts = in_sizes[0] / 3;

    void* histPtr = nullptr;
    cudaGetSymbolAddress(&histPtr, g_hist);
    cudaMemsetAsync(histPtr, 0, NBUCK * sizeof(unsigned));

    PrepArgs a;
    for (int i = 0; i < 9; i++) a.p[i] = (const float*)d_in[2 + i];
    a.lc0 = lc0;
    a.pts = pts;
    a.aabb = aabb;
    a.n = npts;

    if (npts <= MAXN) {
        int histBlocks = (npts + 255) / 256;
        prep_kernel<<<LC0_BLK_END + histBlocks, 256>>>(a);
        scan1_kernel<<<32, 1024>>>();
        scatter_kernel<<<(npts + 255) / 256, 256>>>(pts, aabb, npts);
    } else {
        a.n = 0;
        prep_kernel<<<LC0_BLK_END, 256>>>(a);
        ident_kernel<<<(npts + 255) / 256, 256>>>(pts, aabb, npts);
    }

    int blocks = (npts + 63) / 64;    // 8 pts/warp * 8 warps
    field_kernel<<<blocks, 256>>>(ks, kpb, out, npts);
}

// round 17
// speedup vs baseline: 1.3578x; 1.3578x over previous
#include <cuda_runtime.h>
#include <cuda_fp16.h>

// ---------------------------------------------------------------------------
// KPlaneRBFField on GB300 — round 17.
//  R15 exact (32^3 sort — R16 proved 64^3 causes L1tex same-line contention),
//  plus: field kernel at 1024 threads/block (1 full-RF block/SM): 256
//  consecutive sorted points share one L1D -> scale-0/1 corner loads become
//  L1 hits instead of L2 trips.
// ---------------------------------------------------------------------------

#define NSIDE 64
#define MAXN  524288
#define NBUCK 32768
#define TP_POS 256

__device__ __half   g_planesTh[33030144];  // 66 MB transposed fp16 planes
__device__ __half   g_lc0h[8388608];       // 16.5 MB fp16 codes
__device__ unsigned g_hist[NBUCK];
__device__ unsigned g_blksum[32];
__device__ unsigned g_key[MAXN];
__device__ float4   g_spts[MAXN];          // sorted (xs0,xs1,xs2,pid)

__constant__ int c_plane_off[9] = {
    0,        524288,   1048576,
    1572864,  3670016,  5767168,
    7864320,  16252928, 24641536
};
// blocks/plane @256 pos: {64,64,64,256,256,256,1024,1024,1024}
__constant__ int c_blkCum[10] = {0,64,128,192,448,704,960,1984,3008,4032};
__constant__ int c_res[9]     = {128,128,128,256,256,256,512,512,512};

#define LC0_BLK_END 12224   // 4032 + 8192

struct PrepArgs {
    const float* p[9];
    const float* lc0;
    const float* pts;
    const float* aabb;
    int n;
};

__device__ __forceinline__ unsigned spread3(unsigned x)
{
    x &= 0x3FF;
    x = (x | (x << 16)) & 0x30000FF;
    x = (x | (x << 8))  & 0x300F00F;
    x = (x | (x << 4))  & 0x30C30C3;
    x = (x | (x << 2))  & 0x9249249;
    return x;
}

// ---------------- k1: transpose + lc0 convert + histogram -------------------
__global__ void __launch_bounds__(256) prep_kernel(PrepArgs a)
{
    int b = blockIdx.x;
    int tid = threadIdx.x;

    if (b >= LC0_BLK_END) {                 // Morton histogram (32/dim)
        int i = (b - LC0_BLK_END) * 256 + tid;
        if (i >= a.n) return;
        float a0x = a.aabb[0], a0y = a.aabb[1], a0z = a.aabb[2];
        float a1x = a.aabb[3], a1y = a.aabb[4], a1z = a.aabb[5];
        float x = (a.pts[3 * i + 0] - a0x) * (2.0f / (a1x - a0x)) - 1.0f;
        float y = (a.pts[3 * i + 1] - a0y) * (2.0f / (a1y - a0y)) - 1.0f;
        float z = (a.pts[3 * i + 2] - a0z) * (2.0f / (a1z - a0z)) - 1.0f;
        int qx = min(max((int)((x + 1.0f) * 16.0f), 0), 31);
        int qy = min(max((int)((y + 1.0f) * 16.0f), 0), 31);
        int qz = min(max((int)((z + 1.0f) * 16.0f), 0), 31);
        unsigned key = (spread3(qx) << 2) | (spread3(qy) << 1) | spread3(qz);
        g_key[i] = key;
        atomicAdd(&g_hist[key], 1u);
        return;
    }
    if (b >= 4032) {                        // lc0 convert (8192 blocks)
        int i = (b - 4032) * 256 + tid;
        float4 v = __ldcs((const float4*)a.lc0 + i);
        __half2 h0 = __floats2half2_rn(v.x, v.y);
        __half2 h1 = __floats2half2_rn(v.z, v.w);
        ((uint2*)g_lc0h)[i] = make_uint2(*(unsigned*)&h0, *(unsigned*)&h1);
        return;
    }

    // plane transpose: 256 positions per block, conflict-free smem.
    __shared__ float tile[TP_POS][33];
    int pi = 0;
    #pragma unroll
    for (int i = 1; i < 9; i++) pi += (b >= c_blkCum[i]) ? 1 : 0;
    int rr = c_res[pi] * c_res[pi];
    int posBase = (b - c_blkCum[pi]) * TP_POS;
    const float* src = a.p[pi];

    float va[32];
    #pragma unroll
    for (int it = 0; it < 32; it++)
        va[it] = __ldcs(&src[it * rr + posBase + tid]);
    #pragma unroll
    for (int it = 0; it < 32; it++)
        tile[tid][it] = va[it];
    __syncthreads();

    uint2* dst2 = (uint2*)(g_planesTh + c_plane_off[pi]) + posBase * 8;
    #pragma unroll
    for (int it = 0; it < 8; it++) {
        int v  = tid + it * 256;            // = p*8 + c4idx
        int p  = v >> 3;
        int c4 = (v & 7) << 2;
        __half2 h0 = __floats2half2_rn(tile[p][c4 + 0], tile[p][c4 + 1]);
        __half2 h1 = __floats2half2_rn(tile[p][c4 + 2], tile[p][c4 + 3]);
        dst2[v] = make_uint2(*(unsigned*)&h0, *(unsigned*)&h1);
    }
}

// ---------------- k2: scan ---------------------------------------------------
__global__ void __launch_bounds__(1024) scan1_kernel()
{
    __shared__ unsigned wsum[32];
    int t = threadIdx.x;
    int lane = t & 31;
    int wid = t >> 5;
    int i = blockIdx.x * 1024 + t;
    unsigned v = g_hist[i];

    unsigned x = v;
    #pragma unroll
    for (int off = 1; off < 32; off <<= 1) {
        unsigned y = __shfl_up_sync(0xFFFFFFFFu, x, off);
        if (lane >= off) x += y;
    }
    if (lane == 31) wsum[wid] = x;
    __syncthreads();
    if (wid == 0) {
        unsigned w = wsum[lane];
        unsigned ww = w;
        #pragma unroll
        for (int off = 1; off < 32; off <<= 1) {
            unsigned y = __shfl_up_sync(0xFFFFFFFFu, ww, off);
            if (lane >= off) ww += y;
        }
        wsum[lane] = ww - w;
        if (lane == 31) g_blksum[blockIdx.x] = ww;
    }
    __syncthreads();
    g_hist[i] = x + wsum[wid] - v;
}

// ---------------- k3: scatter -------------------------------------------------
__global__ void scatter_kernel(const float* __restrict__ pts,
                               const float* __restrict__ aabb, int n)
{
    __shared__ unsigned blkoff[32];
    int t = threadIdx.x;
    if (t < 32) {
        unsigned v = g_blksum[t];
        unsigned x = v;
        #pragma unroll
        for (int off = 1; off < 32; off <<= 1) {
            unsigned y = __shfl_up_sync(0xFFFFFFFFu, x, off);
            if (t >= off) x += y;
        }
        blkoff[t] = x - v;
    }
    __syncthreads();

    int i = blockIdx.x * blockDim.x + t;
    if (i >= n) return;
    unsigned key = g_key[i];
    unsigned pos = atomicAdd(&g_hist[key], 1u) + blkoff[key >> 10];

    float a0x = aabb[0], a0y = aabb[1], a0z = aabb[2];
    float a1x = aabb[3], a1y = aabb[4], a1z = aabb[5];
    float xs0 = (pts[3 * i + 0] - a0x) * (2.0f / (a1x - a0x)) - 1.0f;
    float xs1 = (pts[3 * i + 1] - a0y) * (2.0f / (a1y - a0y)) - 1.0f;
    float xs2 = (pts[3 * i + 2] - a0z) * (2.0f / (a1z - a0z)) - 1.0f;
    g_spts[pos] = make_float4(xs0, xs1, xs2, __int_as_float(i));
}

__global__ void ident_kernel(const float* __restrict__ pts,
                             const float* __restrict__ aabb, int n)
{
    int i = blockIdx.x * blockDim.x + threadIdx.x;
    if (i >= n) return;
    float a0x = aabb[0], a0y = aabb[1], a0z = aabb[2];
    float a1x = aabb[3], a1y = aabb[4], a1z = aabb[5];
    float xs0 = (pts[3 * i + 0] - a0x) * (2.0f / (a1x - a0x)) - 1.0f;
    float xs1 = (pts[3 * i + 1] - a0y) * (2.0f / (a1y - a0y)) - 1.0f;
    float xs2 = (pts[3 * i + 2] - a0z) * (2.0f / (a1z - a0z)) - 1.0f;
    g_spts[i] = make_float4(xs0, xs1, xs2, __int_as_float(i));
}

// ---------------- fp16 helpers ----------------------------------------------
__device__ __forceinline__ void h8tof8(uint4 u, float* f)
{
    float2 p;
    p = __half22float2(*(const __half2*)&u.x); f[0] = p.x; f[1] = p.y;
    p = __half22float2(*(const __half2*)&u.y); f[2] = p.x; f[3] = p.y;
    p = __half22float2(*(const __half2*)&u.z); f[4] = p.x; f[5] = p.y;
    p = __half22float2(*(const __half2*)&u.w); f[6] = p.x; f[7] = p.y;
}

// one bilinear sample of 8 channels: 4 LDG.128, x-lerp half2, y-lerp fp32.
__device__ __forceinline__ void sample8(const __half* __restrict__ T, int r,
                                        float u, float v, int c8, float* f)
{
    float fr = (float)(r - 1);
    float fx = (u + 1.0f) * 0.5f * fr;
    float fy = (v + 1.0f) * 0.5f * fr;
    float flx = fminf(fmaxf(floorf(fx), 0.0f), (float)(r - 2));
    float fly = fminf(fmaxf(floorf(fy), 0.0f), (float)(r - 2));
    float wx = fx - flx;
    float wy = fy - fly;
    int ix = (int)flx;
    int iy = (int)fly;
    const uint4* b = (const uint4*)(T + ((iy * r + ix) << 5)) + c8;
    int rs = r << 2;
    uint4 A = __ldg(b);
    uint4 B = __ldg(b + 4);
    uint4 C = __ldg(b + rs);
    uint4 D = __ldg(b + rs + 4);

    __half2 wx2 = __float2half2_rn(wx);
    const __half2* Ah = (const __half2*)&A;
    const __half2* Bh = (const __half2*)&B;
    const __half2* Ch = (const __half2*)&C;
    const __half2* Dh = (const __half2*)&D;
    #pragma unroll
    for (int i = 0; i < 4; i++) {
        __half2 t = __hfma2(__hsub2(Bh[i], Ah[i]), wx2, Ah[i]);
        __half2 o = __hfma2(__hsub2(Dh[i], Ch[i]), wx2, Ch[i]);
        float2 tf = __half22float2(t);
        float2 bf = __half22float2(o);
        f[2 * i + 0] = tf.x + (bf.x - tf.x) * wy;
        f[2 * i + 1] = tf.y + (bf.y - tf.y) * wy;
    }
}

// ---------------- k4: field kernel: 8 pts/warp, 1024 thr/block ----------------
__global__ void __launch_bounds__(1024, 1) field_kernel(
    const float* __restrict__ ks,
    const float* __restrict__ kpb,
    float* __restrict__ out,
    int npts)
{
    int gwarp = (int)((blockIdx.x * blockDim.x + threadIdx.x) >> 5);
    int lane  = threadIdx.x & 31;
    int pslot = lane >> 2;
    int c8    = lane & 3;

    int slot = gwarp * 8 + pslot;
    if (slot >= npts) return;

    float4 sp = __ldcs(&g_spts[slot]);
    float xs0 = sp.x, xs1 = sp.y, xs2 = sp.z;
    int pid = __float_as_int(sp.w);

    float* outP = out + (size_t)pid * 128;
    const float4* kpb4 = (const float4*)kpb;

    const int resArr[3] = {128, 256, 512};
    #pragma unroll
    for (int s = 0; s < 3; s++) {
        int r = resArr[s];
        float f0[8], f1[8], f2[8];
        sample8(g_planesTh + c_plane_off[s * 3 + 0], r, xs0, xs1, c8, f0);
        sample8(g_planesTh + c_plane_off[s * 3 + 1], r, xs0, xs2, c8, f1);
        sample8(g_planesTh + c_plane_off[s * 3 + 2], r, xs1, xs2, c8, f2);
        float4 bb0 = __ldg(kpb4 + s * 8 + c8 * 2);
        float4 bb1 = __ldg(kpb4 + s * 8 + c8 * 2 + 1);
        float4 o0, o1;
        o0.x = f0[0] * f1[0] * f2[0] + bb0.x;
        o0.y = f0[1] * f1[1] * f2[1] + bb0.y;
        o0.z = f0[2] * f1[2] * f2[2] + bb0.z;
        o0.w = f0[3] * f1[3] * f2[3] + bb0.w;
        o1.x = f0[4] * f1[4] * f2[4] + bb1.x;
        o1.y = f0[5] * f1[5] * f2[5] + bb1.y;
        o1.z = f0[6] * f1[6] * f2[6] + bb1.z;
        o1.w = f0[7] * f1[7] * f2[7] + bb1.w;
        float* op = outP + s * 32 + (c8 << 3);
        __stcs((float4*)op, o0);
        __stcs((float4*)(op + 4), o1);
    }

    // ---- RBF features over 64^3 grid on [-1,1]
    const float interval = 2.0f / (float)(NSIDE - 1);
    float c0f = fminf(fmaxf(floorf((xs0 + 1.0f) / interval), 0.0f), (float)(NSIDE - 2));
    float c1f = fminf(fmaxf(floorf((xs1 + 1.0f) / interval), 0.0f), (float)(NSIDE - 2));
    float c2f = fminf(fmaxf(floorf((xs2 + 1.0f) / interval), 0.0f), (float)(NSIDE - 2));
    int ci0 = (int)c0f, ci1 = (int)c1f, ci2 = (int)c2f;

    float acc[8] = {0.f, 0.f, 0.f, 0.f, 0.f, 0.f, 0.f, 0.f};
    float wsum = 0.0f;
    #pragma unroll
    for (int g = 0; g < 2; g++) {
        int idxA[4];
        float d2A[4];
        #pragma unroll
        for (int q = 0; q < 4; q++) {
            int k = g * 4 + q;
            int i0 = ci0 + ((k >> 2) & 1);
            int i1 = ci1 + ((k >> 1) & 1);
            int i2 = ci2 + (k & 1);
            idxA[q] = (i0 * NSIDE + i1) * NSIDE + i2;
            float d0 = xs0 - (-1.0f + (float)i0 * interval);
            float d1 = xs1 - (-1.0f + (float)i1 * interval);
            float d2 = xs2 - (-1.0f + (float)i2 * interval);
            d2A[q] = d0 * d0 + d1 * d1 + d2 * d2;
        }
        float svA[4];
        uint4 cuA[4];
        #pragma unroll
        for (int q = 0; q < 4; q++) {
            svA[q] = __ldg(&ks[idxA[q]]);
            cuA[q] = __ldg((const uint4*)(g_lc0h + (idxA[q] << 5)) + c8);
        }
        #pragma unroll
        for (int q = 0; q < 4; q++) {
            float phi = 1.0f / (1.0f + d2A[q] * svA[q] * svA[q]);
            wsum += phi;
            float code[8];
            h8tof8(cuA[q], code);
            #pragma unroll
            for (int j = 0; j < 8; j++) acc[j] += phi * code[j];
        }
    }
    float inv = 1.0f / (wsum + 1e-8f);
    float4 bb0 = __ldg(kpb4 + 24 + c8 * 2);
    float4 bb1 = __ldg(kpb4 + 24 + c8 * 2 + 1);
    float4 o0, o1;
    o0.x = acc[0] * inv + bb0.x;
    o0.y = acc[1] * inv + bb0.y;
    o0.z = acc[2] * inv + bb0.z;
    o0.w = acc[3] * inv + bb0.w;
    o1.x = acc[4] * inv + bb1.x;
    o1.y = acc[5] * inv + bb1.y;
    o1.z = acc[6] * inv + bb1.z;
    o1.w = acc[7] * inv + bb1.w;
    float* op = outP + 96 + (c8 << 3);
    __stcs((float4*)op, o0);
    __stcs((float4*)(op + 4), o1);
}

// ------------------------------ launcher ------------------------------------
extern "C" void kernel_launch(void* const* d_in, const int* in_sizes, int n_in,
                              void* d_out, int out_size)
{
    const float* pts  = (const float*)d_in[0];
    const float* aabb = (const float*)d_in[1];
    const float* lc0  = (const float*)d_in[11];
    const float* ks   = (const float*)d_in[12];
    const float* kpb  = (const float*)d_in[13];
    float* out = (float*)d_out;

    int npts = in_sizes[0] / 3;

    void* histPtr = nullptr;
    cudaGetSymbolAddress(&histPtr, g_hist);
    cudaMemsetAsync(histPtr, 0, NBUCK * sizeof(unsigned));

    PrepArgs a;
    for (int i = 0; i < 9; i++) a.p[i] = (const float*)d_in[2 + i];
    a.lc0 = lc0;
    a.pts = pts;
    a.aabb = aabb;
    a.n = npts;

    if (npts <= MAXN) {
        int histBlocks = (npts + 255) / 256;
        prep_kernel<<<LC0_BLK_END + histBlocks, 256>>>(a);
        scan1_kernel<<<32, 1024>>>();
        scatter_kernel<<<(npts + 255) / 256, 256>>>(pts, aabb, npts);
    } else {
        a.n = 0;
        prep_kernel<<<LC0_BLK_END, 256>>>(a);
        ident_kernel<<<(npts + 255) / 256, 256>>>(pts, aabb, npts);
    }

    // 8 pts/warp, 32 warps/block -> 256 points per block
    int blocks = (npts + 255) / 256;
    field_kernel<<<blocks, 1024>>>(ks, kpb, out, npts);
}